// round 2
// baseline (speedup 1.0000x reference)
#include <cuda_runtime.h>
#include <cstdint>

// Reference is a degenerate conv:
//   out(n,f,i,j) = bias[f] + sum_{a,b} w[f,2,a,b] * x[n,0,i+a,j+b]
//   x: (16,3,256,256) f32, w: (64,3,3,3) f32, b: (64,) f32
//   out: (16,64,254,254) f32
#define NB    16
#define F_OUT 64
#define Hh    256
#define Ww    256
#define HO    254
#define WO    254
#define IP    (HO / 2)            // 127 row-pairs (i = 2*ip, even)
#define JQ4   63                  // 4-wide col tiles covering j = 0..251
#define N_MAIN (NB * IP * JQ4)    // 128016 threads, 2x4 patches
#define N_TAIL (NB * IP)          // 2032 threads, 2x2 patch at j=252
#define N_TOT  (N_MAIN + N_TAIL)  // 130048 = 508 * 256 exactly

typedef unsigned long long u64;

// packed f32x2 FMA (Blackwell): d = a * w + c on both lanes
static __device__ __forceinline__ u64 ffma2(u64 a, u64 w, u64 c) {
    u64 d;
    asm("fma.rn.f32x2 %0, %1, %2, %3;" : "=l"(d) : "l"(a), "l"(w), "l"(c));
    return d;
}

static __device__ __forceinline__ u64 pack2(float lo, float hi) {
    u64 d;
    asm("mov.b64 %0, {%1, %2};" : "=l"(d) : "f"(lo), "f"(hi));
    return d;
}

// streaming stores (evict-first): output is write-once, don't pollute L2
static __device__ __forceinline__ void stcs128(float* p, u64 a, u64 b) {
    asm volatile("st.global.cs.v2.b64 [%0], {%1, %2};"
                 :: "l"(p), "l"(a), "l"(b) : "memory");
}
static __device__ __forceinline__ void stcs64(float* p, u64 a) {
    asm volatile("st.global.cs.b64 [%0], %1;"
                 :: "l"(p), "l"(a) : "memory");
}

__global__ __launch_bounds__(256) void conv2dcq_kernel(
    const float* __restrict__ x,
    const float* __restrict__ w,
    const float* __restrict__ bias,
    float* __restrict__ out) {

    // Weights duplicated to (w,w) f32x2 in smem; bias likewise.
    __shared__ u64 sw[F_OUT * 9];
    __shared__ u64 sb[F_OUT];

    const int tid = threadIdx.x;
    for (int t = tid; t < F_OUT * 9; t += blockDim.x) {
        const float v = w[(t / 9) * 27 + 18 + (t % 9)];   // w[f, 2, a, b]
        sw[t] = pack2(v, v);
    }
    if (tid < F_OUT) {
        const float v = bias[tid];
        sb[tid] = pack2(v, v);
    }
    __syncthreads();

    const int idx = blockIdx.x * blockDim.x + tid;
    if (idx >= N_TOT) return;

    if (idx < N_MAIN) {
        // ---- main path: 2 rows x 4 cols per thread ----
        const int jq = idx % JQ4;
        const int t2 = idx / JQ4;
        const int ip = t2 % IP;
        const int n  = t2 / IP;
        const int i  = ip * 2;        // even
        const int j  = jq * 4;        // multiple of 4

        const float* xb = x + (size_t)n * 3 * Hh * Ww + (size_t)i * Ww + j;

        // P[r][s] = (x[i+r][j+s], x[i+r][j+s+1]), r=0..3, s=0..4
        u64 P[4][5];
        #pragma unroll
        for (int r = 0; r < 4; r++) {
            const float4 lo = *reinterpret_cast<const float4*>(xb + (size_t)r * Ww);
            const float2 hi = *reinterpret_cast<const float2*>(xb + (size_t)r * Ww + 4);
            P[r][0] = pack2(lo.x, lo.y);
            P[r][1] = pack2(lo.y, lo.z);
            P[r][2] = pack2(lo.z, lo.w);
            P[r][3] = pack2(lo.w, hi.x);
            P[r][4] = pack2(hi.x, hi.y);
        }

        float* ob = out + (size_t)n * F_OUT * HO * WO + (size_t)i * WO + j;

        #pragma unroll 2
        for (int f = 0; f < F_OUT; f++) {
            const u64 bb = sb[f];
            u64 a00 = bb, a01 = bb;   // row i,   cols j..j+1 / j+2..j+3
            u64 a10 = bb, a11 = bb;   // row i+1
            const u64* wf = &sw[f * 9];
            #pragma unroll
            for (int a = 0; a < 3; a++) {
                #pragma unroll
                for (int b = 0; b < 3; b++) {
                    const u64 wv = wf[a * 3 + b];
                    a00 = ffma2(P[a][b],         wv, a00);
                    a01 = ffma2(P[a][b + 2],     wv, a01);
                    a10 = ffma2(P[a + 1][b],     wv, a10);
                    a11 = ffma2(P[a + 1][b + 2], wv, a11);
                }
            }
            // row i: base ≡ 0 mod 16B -> STG.128; row i+1: offset by 254 floats
            // (≡ 8B), only 8B-aligned -> 2x STG.64.
            stcs128(ob, a00, a01);
            stcs64(ob + WO,     a10);
            stcs64(ob + WO + 2, a11);
            ob += (size_t)HO * WO;
        }
    } else {
        // ---- tail path: 2 rows x 2 cols at j = 252 ----
        const int t2 = idx - N_MAIN;
        const int ip = t2 % IP;
        const int n  = t2 / IP;
        const int i  = ip * 2;
        const int j  = 252;

        const float* xb = x + (size_t)n * 3 * Hh * Ww + (size_t)i * Ww + j;

        u64 P[4][3];
        #pragma unroll
        for (int r = 0; r < 4; r++) {
            const float4 v = *reinterpret_cast<const float4*>(xb + (size_t)r * Ww);
            P[r][0] = pack2(v.x, v.y);
            P[r][1] = pack2(v.y, v.z);
            P[r][2] = pack2(v.z, v.w);
        }

        float* ob = out + (size_t)n * F_OUT * HO * WO + (size_t)i * WO + j;

        #pragma unroll 2
        for (int f = 0; f < F_OUT; f++) {
            const u64 bb = sb[f];
            u64 a0 = bb, a1 = bb;
            const u64* wf = &sw[f * 9];
            #pragma unroll
            for (int a = 0; a < 3; a++) {
                #pragma unroll
                for (int b = 0; b < 3; b++) {
                    const u64 wv = wf[a * 3 + b];
                    a0 = ffma2(P[a][b],     wv, a0);
                    a1 = ffma2(P[a + 1][b], wv, a1);
                }
            }
            stcs64(ob,      a0);
            stcs64(ob + WO, a1);
            ob += (size_t)HO * WO;
        }
    }
}

extern "C" void kernel_launch(void* const* d_in, const int* in_sizes, int n_in,
                              void* d_out, int out_size) {
    const float* x    = (const float*)d_in[0];
    const float* w    = (const float*)d_in[1];
    const float* bias = (const float*)d_in[2];
    float* out        = (float*)d_out;

    const int block = 256;
    const int grid  = (N_TOT + block - 1) / block;   // 508
    conv2dcq_kernel<<<grid, block>>>(x, w, bias, out);
}

// round 3
// speedup vs baseline: 1.6258x; 1.6258x over previous
#include <cuda_runtime.h>
#include <cstdint>

// Degenerate conv (reference uses only x[:,0] and w[:,2]):
//   out(n,f,i,j) = bias[f] + sum_{a,b} w[f,2,a,b] * x[n,0,i+a,j+b]
//   x: (16,3,256,256) f32, w: (64,3,3,3) f32, b: (64,) f32
//   out: (16,64,254,254) f32
#define NB     16
#define F_OUT  64
#define F_HALF 32                 // filters per thread (f-loop split in 2)
#define Hh     256
#define Ww     256
#define HO     254
#define WO     254
#define IP     (HO / 2)           // 127 row-pairs (i even)
#define JP     (WO / 2)           // 127 col-pairs (j even)
#define N_SPATIAL (NB * IP * JP)  // 258064 spatial 2x2 patches
#define N_TOT     (N_SPATIAL * 2) // 516128 threads (x2 filter halves)

typedef unsigned long long u64;

// packed f32x2 FMA (Blackwell): d = a * w + c on both lanes
static __device__ __forceinline__ u64 ffma2(u64 a, u64 w, u64 c) {
    u64 d;
    asm("fma.rn.f32x2 %0, %1, %2, %3;" : "=l"(d) : "l"(a), "l"(w), "l"(c));
    return d;
}

static __device__ __forceinline__ u64 pack2(float lo, float hi) {
    u64 d;
    asm("mov.b64 %0, {%1, %2};" : "=l"(d) : "f"(lo), "f"(hi));
    return d;
}

__global__ __launch_bounds__(256) void conv2dcq_kernel(
    const float* __restrict__ x,
    const float* __restrict__ w,
    const float* __restrict__ bias,
    float* __restrict__ out) {

    // Weights duplicated to (w,w) f32x2 in smem; bias likewise.
    __shared__ u64 sw[F_OUT * 9];
    __shared__ u64 sb[F_OUT];

    const int tid = threadIdx.x;
    for (int t = tid; t < F_OUT * 9; t += blockDim.x) {
        const float v = w[(t / 9) * 27 + 18 + (t % 9)];   // w[f, 2, a, b]
        sw[t] = pack2(v, v);
    }
    if (tid < F_OUT) {
        const float v = bias[tid];
        sb[tid] = pack2(v, v);
    }
    __syncthreads();

    const int idx = blockIdx.x * blockDim.x + tid;
    if (idx >= N_TOT) return;

    // Filter half is the SLOWEST dim: warps stay spatially coherent.
    const int sp = (idx < N_SPATIAL) ? idx : (idx - N_SPATIAL);
    const int f0 = (idx < N_SPATIAL) ? 0 : F_HALF;

    const int jp = sp % JP;
    const int t2 = sp / JP;
    const int ip = t2 % IP;
    const int n  = t2 / IP;
    const int i  = ip * 2;        // even
    const int j  = jp * 2;        // even

    // Input channel 0: 4 rows x 4 cols for a 2x2 output patch.
    const float* xb = x + (size_t)n * 3 * Hh * Ww + (size_t)i * Ww + j;

    // P[r][b] = (x[i+r][j+b], x[i+r][j+b+1]) packed f32x2
    u64 P[4][3];
    #pragma unroll
    for (int r = 0; r < 4; r++) {
        // j even -> 8B-aligned float2 loads
        const float2 lo = *reinterpret_cast<const float2*>(xb + (size_t)r * Ww);
        const float2 hi = *reinterpret_cast<const float2*>(xb + (size_t)r * Ww + 2);
        P[r][0] = pack2(lo.x, lo.y);
        P[r][1] = pack2(lo.y, hi.x);
        P[r][2] = pack2(hi.x, hi.y);
    }

    float* ob = out + (size_t)n * F_OUT * HO * WO
                    + (size_t)f0 * HO * WO
                    + (size_t)i * WO + j;

    #pragma unroll 4
    for (int f = f0; f < f0 + F_HALF; f++) {
        u64 a0 = sb[f];
        u64 a1 = a0;
        const u64* wf = &sw[f * 9];
        #pragma unroll
        for (int a = 0; a < 3; a++) {
            #pragma unroll
            for (int b = 0; b < 3; b++) {
                const u64 wv = wf[a * 3 + b];    // LDS.64 broadcast
                a0 = ffma2(P[a][b],     wv, a0);
                a1 = ffma2(P[a + 1][b], wv, a1);
            }
        }
        // 8B-aligned: row stride 254*4 = 1016 B (8B multiple), j even
        *reinterpret_cast<u64*>(ob)      = a0;
        *reinterpret_cast<u64*>(ob + WO) = a1;
        ob += (size_t)HO * WO;
    }
}

extern "C" void kernel_launch(void* const* d_in, const int* in_sizes, int n_in,
                              void* d_out, int out_size) {
    const float* x    = (const float*)d_in[0];
    const float* w    = (const float*)d_in[1];
    const float* bias = (const float*)d_in[2];
    float* out        = (float*)d_out;

    const int block = 256;
    const int grid  = (N_TOT + block - 1) / block;   // 2017
    conv2dcq_kernel<<<grid, block>>>(x, w, bias, out);
}